// round 4
// baseline (speedup 1.0000x reference)
#include <cuda_runtime.h>
#include <cuda_bf16.h>

#define DIM     128
#define ROWV    32            // float4 per full row
#define SLICE_V 8             // float4 per D-slice (32 floats)
#define NSLICE  4             // DIM / 32
#define S3_THREADS 512
#define ENT_PER_ITER (S3_THREADS / SLICE_V)   // 64 entities per CTA iteration
#define S3_GRIDX 37           // 37 * 4 slices = 148 CTAs = 1 per SM

// ---------------------------------------------------------------------------
// Kernel 1 (sub2): one block of 512 threads per type node c.
// 4 groups x 128 threads sum slices of the deg2 edge segment; smem reduce.
// ---------------------------------------------------------------------------
__global__ __launch_bounds__(512)
void sub2_kernel(const float* __restrict__ emb,
                 const int*   __restrict__ s2row,
                 const int*   __restrict__ lspec,
                 const int*   __restrict__ rcom,
                 float*       __restrict__ out,
                 float addc, int deg2)
{
    __shared__ float part[4][DIM];

    const int c = blockIdx.x;
    const int d = threadIdx.x & (DIM - 1);
    const int g = threadIdx.x >> 7;

    const int* __restrict__ e = s2row + (size_t)c * deg2;
    const int chunk = deg2 >> 2;
    const int j0 = g * chunk;
    const int j1 = (g == 3) ? deg2 : j0 + chunk;

    float acc = 0.0f;
    #pragma unroll 8
    for (int j = j0; j < j1; ++j) {
        int src = __ldg(&lspec[__ldg(&e[j])]);
        acc += __ldcs(&emb[(size_t)src * DIM + d]);
    }
    part[g][d] = acc;
    __syncthreads();

    if (g == 0) {
        const int tgt = rcom[c];
        float v = __ldg(&emb[(size_t)tgt * DIM + d])
                + part[0][d] + part[1][d] + part[2][d] + part[3][d] + addc;
        out[(size_t)tgt * DIM + d] = v;   // default store: keep hot for sub3 fill
    }
}

// ---------------------------------------------------------------------------
// Kernel 2 (sub3), deg3==4 smem-table path.
// grid = (S3_GRIDX, NSLICE). Each CTA owns D-slice blockIdx.y (32 floats) and
// an entity range. It first stages its slice of ALL n_typ updated type rows
// (table[j] = out[lcom[j]], 128 KB) in shared memory, then streams entities:
// per entity: int4 edge load, 4 conflict-free LDS.128 gathers, 1 streaming
// float4 read of emb, 1 streaming float4 write of out. Zero global gather
// traffic in the hot loop.
// ---------------------------------------------------------------------------
extern __shared__ float4 s_typ[];   // [n_typ * SLICE_V]

__global__ __launch_bounds__(S3_THREADS)
void sub3_smem(const float4* __restrict__ emb4,
               const int4*   __restrict__ edges4,
               const int*    __restrict__ lcom,
               const int*    __restrict__ rspec,
               float4*       __restrict__ out4,
               int n_ent, int n_typ, float add, float inv_sum)
{
    const int sbase = blockIdx.y * SLICE_V;      // float4 offset within row
    const int tid   = threadIdx.x;
    const int sub   = tid & (SLICE_V - 1);       // 0..7 chunk within slice
    const int eoff  = tid >> 3;                  // 0..63 entity offset

    // ---- stage type-table slice ----
    for (int i = tid; i < n_typ * SLICE_V; i += S3_THREADS) {
        const int j = i >> 3;
        const int c = i & (SLICE_V - 1);
        const int gidx = __ldg(&lcom[j]);
        s_typ[i] = __ldg(&out4[(size_t)gidx * ROWV + sbase + c]);
    }
    __syncthreads();

    // ---- entity range ----
    const int per = (n_ent + gridDim.x - 1) / gridDim.x;
    const int e0  = blockIdx.x * per;
    const int e1  = min(e0 + per, n_ent);
    const int span = e1 - e0;
    if (span <= 0) return;
    const int full = span / ENT_PER_ITER * ENT_PER_ITER;

    // ---- main streaming loop (no bounds check) ----
    int eb = e0;
    #pragma unroll 2
    for (; eb < e0 + full; eb += ENT_PER_ITER) {
        const int ent = eb + eoff;
        const int4 e = __ldg(&edges4[ent]);
        const int r  = __ldg(&rspec[ent]);
        float4 iv = __ldcs(&emb4[(size_t)r * ROWV + sbase + sub]);
        float4 g0 = s_typ[e.x * SLICE_V + sub];
        float4 g1 = s_typ[e.y * SLICE_V + sub];
        float4 g2 = s_typ[e.z * SLICE_V + sub];
        float4 g3 = s_typ[e.w * SLICE_V + sub];
        float4 a, w;
        a.x = (g0.x + g1.x) + (g2.x + g3.x);
        a.y = (g0.y + g1.y) + (g2.y + g3.y);
        a.z = (g0.z + g1.z) + (g2.z + g3.z);
        a.w = (g0.w + g1.w) + (g2.w + g3.w);
        w.x = iv.x * (1.0f - (a.x + add) * inv_sum);
        w.y = iv.y * (1.0f - (a.y + add) * inv_sum);
        w.z = iv.z * (1.0f - (a.z + add) * inv_sum);
        w.w = iv.w * (1.0f - (a.w + add) * inv_sum);
        __stcs(&out4[(size_t)r * ROWV + sbase + sub], w);
    }

    // ---- tail ----
    for (; eb < e1; eb += ENT_PER_ITER) {
        const int ent = eb + eoff;
        if (ent < e1) {
            const int4 e = __ldg(&edges4[ent]);
            const int r  = __ldg(&rspec[ent]);
            float4 iv = __ldcs(&emb4[(size_t)r * ROWV + sbase + sub]);
            float4 g0 = s_typ[e.x * SLICE_V + sub];
            float4 g1 = s_typ[e.y * SLICE_V + sub];
            float4 g2 = s_typ[e.z * SLICE_V + sub];
            float4 g3 = s_typ[e.w * SLICE_V + sub];
            float4 a, w;
            a.x = (g0.x + g1.x) + (g2.x + g3.x);
            a.y = (g0.y + g1.y) + (g2.y + g3.y);
            a.z = (g0.z + g1.z) + (g2.z + g3.z);
            a.w = (g0.w + g1.w) + (g2.w + g3.w);
            w.x = iv.x * (1.0f - (a.x + add) * inv_sum);
            w.y = iv.y * (1.0f - (a.y + add) * inv_sum);
            w.z = iv.z * (1.0f - (a.z + add) * inv_sum);
            w.w = iv.w * (1.0f - (a.w + add) * inv_sum);
            __stcs(&out4[(size_t)r * ROWV + sbase + sub], w);
        }
    }
}

// ---------------------------------------------------------------------------
// Generic fallback (any deg3, or n_typ too large for smem): warp per entity.
// ---------------------------------------------------------------------------
__global__ __launch_bounds__(256)
void sub3_kernel_gen(const float* __restrict__ emb,
                     const int*   __restrict__ s3row,
                     const int*   __restrict__ lcom,
                     const int*   __restrict__ rspec,
                     float*       __restrict__ out,
                     int n_ent, float n_typ_f, int deg3)
{
    const int warp = threadIdx.x >> 5;
    const int lane = threadIdx.x & 31;
    const int n = blockIdx.x * (blockDim.x >> 5) + warp;
    if (n >= n_ent) return;

    const float4* __restrict__ out4 = (const float4*)out;
    const int* __restrict__ e = s3row + (size_t)n * deg3;

    float4 acc = make_float4(0.f, 0.f, 0.f, 0.f);
    for (int j = 0; j < deg3; ++j) {
        int t = __ldg(&lcom[__ldg(&e[j])]);
        float4 v = __ldg(&out4[(size_t)t * ROWV + lane]);
        acc.x += v.x; acc.y += v.y; acc.z += v.z; acc.w += v.w;
    }
    const float add     = n_typ_f - (float)deg3;
    const float inv_sum = 1.0f / (1.0f + (float)deg3);
    const int   tgt     = rspec[n];
    float4 iv = __ldcs(&((const float4*)emb)[(size_t)tgt * ROWV + lane]);
    float4 r;
    r.x = iv.x * (1.0f - (acc.x + add) * inv_sum);
    r.y = iv.y * (1.0f - (acc.y + add) * inv_sum);
    r.z = iv.z * (1.0f - (acc.z + add) * inv_sum);
    r.w = iv.w * (1.0f - (acc.w + add) * inv_sum);
    __stcs(&((float4*)out)[(size_t)tgt * ROWV + lane], r);
}

// ---------------------------------------------------------------------------
// Launch. Inputs (metadata order):
//  0 all_node_embedding f32 | 1 sub2_row | 2 sub2_col | 3 sub3_row | 4 sub3_col
//  5 left_specific | 6 right_common | 7 left_common | 8 right_specific
// ---------------------------------------------------------------------------
extern "C" void kernel_launch(void* const* d_in, const int* in_sizes, int n_in,
                              void* d_out, int out_size)
{
    const float* emb   = (const float*)d_in[0];
    const int*   s2row = (const int*)  d_in[1];
    const int*   s3row = (const int*)  d_in[3];
    const int*   lspec = (const int*)  d_in[5];
    const int*   rcom  = (const int*)  d_in[6];
    const int*   lcom  = (const int*)  d_in[7];
    const int*   rspec = (const int*)  d_in[8];
    float*       out   = (float*)d_out;

    const int n_ent = in_sizes[5];
    const int n_typ = in_sizes[6];
    const int deg2  = in_sizes[1] / n_typ;
    const int deg3  = in_sizes[3] / in_sizes[8];

    // ---- sub2 ----
    sub2_kernel<<<n_typ, 512>>>(emb, s2row, lspec, rcom, out,
                                (float)n_ent - (float)deg2, deg2);

    // ---- sub3 ----
    const size_t smem_bytes = (size_t)n_typ * SLICE_V * sizeof(float4); // n_typ*128B
    if (deg3 == 4 && smem_bytes <= 226 * 1024) {
        static int attr_set = 0;
        if (!attr_set) {
            cudaFuncSetAttribute(sub3_smem,
                                 cudaFuncAttributeMaxDynamicSharedMemorySize,
                                 226 * 1024);
            attr_set = 1;
        }
        dim3 grid(S3_GRIDX, NSLICE);
        sub3_smem<<<grid, S3_THREADS, smem_bytes>>>(
            (const float4*)emb, (const int4*)s3row, lcom, rspec,
            (float4*)out, n_ent, n_typ,
            (float)n_typ - 4.0f, 1.0f / 5.0f);
    } else {
        const int warps_per_block = 8;
        const int blocks = (n_ent + warps_per_block - 1) / warps_per_block;
        sub3_kernel_gen<<<blocks, warps_per_block * 32>>>(
            emb, s3row, lcom, rspec, out, n_ent, (float)n_typ, deg3);
    }
}

// round 5
// speedup vs baseline: 1.4815x; 1.4815x over previous
#include <cuda_runtime.h>
#include <cuda_bf16.h>

#define DIM     128
#define ROWV    32            // float4 per full row
#define SLICE_V 4             // float4 per D-slice (16 floats)
#define NSLICE  8             // DIM / 16
#define S3_THREADS 512
#define ENT_PER_ITER (S3_THREADS / SLICE_V)   // 128 entities per CTA iteration
#define S3_GRIDX 56           // 56 * 8 slices = 448 CTAs ≈ 3 per SM
#define S3_SMEM_MAX (70 * 1024)

// ---------------------------------------------------------------------------
// Kernel 1 (sub2): one block of 512 threads per type node c.
// 4 groups x 128 threads sum slices of the deg2 edge segment; smem reduce.
// ---------------------------------------------------------------------------
__global__ __launch_bounds__(512)
void sub2_kernel(const float* __restrict__ emb,
                 const int*   __restrict__ s2row,
                 const int*   __restrict__ lspec,
                 const int*   __restrict__ rcom,
                 float*       __restrict__ out,
                 float addc, int deg2)
{
    __shared__ float part[4][DIM];

    const int c = blockIdx.x;
    const int d = threadIdx.x & (DIM - 1);
    const int g = threadIdx.x >> 7;

    const int* __restrict__ e = s2row + (size_t)c * deg2;
    const int chunk = deg2 >> 2;
    const int j0 = g * chunk;
    const int j1 = (g == 3) ? deg2 : j0 + chunk;

    float acc = 0.0f;
    #pragma unroll 8
    for (int j = j0; j < j1; ++j) {
        int src = __ldg(&lspec[__ldg(&e[j])]);
        acc += __ldcs(&emb[(size_t)src * DIM + d]);
    }
    part[g][d] = acc;
    __syncthreads();

    if (g == 0) {
        const int tgt = rcom[c];
        float v = __ldg(&emb[(size_t)tgt * DIM + d])
                + part[0][d] + part[1][d] + part[2][d] + part[3][d] + addc;
        out[(size_t)tgt * DIM + d] = v;   // default store: stays L2-hot for fills
    }
}

// ---------------------------------------------------------------------------
// Kernel 2 (sub3), deg3==4 smem-table path, occupancy-tuned.
// grid = (S3_GRIDX, NSLICE). Each CTA owns a 16-float D-slice and an entity
// range. It stages its slice of all n_typ updated type rows
// (table[j] = out[lcom[j]], 64 KB -> 3 CTAs/SM, 48 warps/SM), then streams
// entities: int4 edge load, 4 conflict-light LDS.128 gathers, 1 streaming
// float4 read, 1 streaming float4 write. No global gather traffic.
// ---------------------------------------------------------------------------
extern __shared__ float4 s_typ[];   // [n_typ * SLICE_V]

__global__ __launch_bounds__(S3_THREADS)
void sub3_smem(const float4* __restrict__ emb4,
               const int4*   __restrict__ edges4,
               const int*    __restrict__ lcom,
               const int*    __restrict__ rspec,
               float4*       __restrict__ out4,
               int n_ent, int n_typ, float add, float inv_sum)
{
    const int sbase = blockIdx.y * SLICE_V;          // float4 offset within row
    const int tid   = threadIdx.x;
    const int sub   = tid & (SLICE_V - 1);           // 0..3 chunk within slice
    const int eoff  = tid >> 2;                      // 0..127 entity offset

    // ---- stage type-table slice (reads are L2-hot: only n_typ*512B distinct) ----
    for (int i = tid; i < n_typ * SLICE_V; i += S3_THREADS) {
        const int j = i >> 2;
        const int c = i & (SLICE_V - 1);
        const int gidx = __ldg(&lcom[j]);
        s_typ[i] = __ldg(&out4[(size_t)gidx * ROWV + sbase + c]);
    }
    __syncthreads();

    // ---- entity range ----
    const int per = (n_ent + gridDim.x - 1) / gridDim.x;
    const int e0  = blockIdx.x * per;
    const int e1  = min(e0 + per, n_ent);
    const int span = e1 - e0;
    if (span <= 0) return;
    const int full = span / ENT_PER_ITER * ENT_PER_ITER;

    // ---- main streaming loop ----
    int eb = e0;
    #pragma unroll 4
    for (; eb < e0 + full; eb += ENT_PER_ITER) {
        const int ent = eb + eoff;
        const int4 e = __ldg(&edges4[ent]);
        const int r  = __ldg(&rspec[ent]);
        float4 iv = __ldcs(&emb4[(size_t)r * ROWV + sbase + sub]);
        float4 g0 = s_typ[e.x * SLICE_V + sub];
        float4 g1 = s_typ[e.y * SLICE_V + sub];
        float4 g2 = s_typ[e.z * SLICE_V + sub];
        float4 g3 = s_typ[e.w * SLICE_V + sub];
        float4 a, w;
        a.x = (g0.x + g1.x) + (g2.x + g3.x);
        a.y = (g0.y + g1.y) + (g2.y + g3.y);
        a.z = (g0.z + g1.z) + (g2.z + g3.z);
        a.w = (g0.w + g1.w) + (g2.w + g3.w);
        w.x = iv.x * (1.0f - (a.x + add) * inv_sum);
        w.y = iv.y * (1.0f - (a.y + add) * inv_sum);
        w.z = iv.z * (1.0f - (a.z + add) * inv_sum);
        w.w = iv.w * (1.0f - (a.w + add) * inv_sum);
        __stcs(&out4[(size_t)r * ROWV + sbase + sub], w);
    }

    // ---- tail ----
    for (; eb < e1; eb += ENT_PER_ITER) {
        const int ent = eb + eoff;
        if (ent < e1) {
            const int4 e = __ldg(&edges4[ent]);
            const int r  = __ldg(&rspec[ent]);
            float4 iv = __ldcs(&emb4[(size_t)r * ROWV + sbase + sub]);
            float4 g0 = s_typ[e.x * SLICE_V + sub];
            float4 g1 = s_typ[e.y * SLICE_V + sub];
            float4 g2 = s_typ[e.z * SLICE_V + sub];
            float4 g3 = s_typ[e.w * SLICE_V + sub];
            float4 a, w;
            a.x = (g0.x + g1.x) + (g2.x + g3.x);
            a.y = (g0.y + g1.y) + (g2.y + g3.y);
            a.z = (g0.z + g1.z) + (g2.z + g3.z);
            a.w = (g0.w + g1.w) + (g2.w + g3.w);
            w.x = iv.x * (1.0f - (a.x + add) * inv_sum);
            w.y = iv.y * (1.0f - (a.y + add) * inv_sum);
            w.z = iv.z * (1.0f - (a.z + add) * inv_sum);
            w.w = iv.w * (1.0f - (a.w + add) * inv_sum);
            __stcs(&out4[(size_t)r * ROWV + sbase + sub], w);
        }
    }
}

// ---------------------------------------------------------------------------
// Generic fallback (any deg3, or n_typ too large for smem): warp per entity.
// ---------------------------------------------------------------------------
__global__ __launch_bounds__(256)
void sub3_kernel_gen(const float* __restrict__ emb,
                     const int*   __restrict__ s3row,
                     const int*   __restrict__ lcom,
                     const int*   __restrict__ rspec,
                     float*       __restrict__ out,
                     int n_ent, float n_typ_f, int deg3)
{
    const int warp = threadIdx.x >> 5;
    const int lane = threadIdx.x & 31;
    const int n = blockIdx.x * (blockDim.x >> 5) + warp;
    if (n >= n_ent) return;

    const float4* __restrict__ out4 = (const float4*)out;
    const int* __restrict__ e = s3row + (size_t)n * deg3;

    float4 acc = make_float4(0.f, 0.f, 0.f, 0.f);
    for (int j = 0; j < deg3; ++j) {
        int t = __ldg(&lcom[__ldg(&e[j])]);
        float4 v = __ldg(&out4[(size_t)t * ROWV + lane]);
        acc.x += v.x; acc.y += v.y; acc.z += v.z; acc.w += v.w;
    }
    const float add     = n_typ_f - (float)deg3;
    const float inv_sum = 1.0f / (1.0f + (float)deg3);
    const int   tgt     = rspec[n];
    float4 iv = __ldcs(&((const float4*)emb)[(size_t)tgt * ROWV + lane]);
    float4 r;
    r.x = iv.x * (1.0f - (acc.x + add) * inv_sum);
    r.y = iv.y * (1.0f - (acc.y + add) * inv_sum);
    r.z = iv.z * (1.0f - (acc.z + add) * inv_sum);
    r.w = iv.w * (1.0f - (acc.w + add) * inv_sum);
    __stcs(&((float4*)out)[(size_t)tgt * ROWV + lane], r);
}

// ---------------------------------------------------------------------------
// Launch. Inputs (metadata order):
//  0 all_node_embedding f32 | 1 sub2_row | 2 sub2_col | 3 sub3_row | 4 sub3_col
//  5 left_specific | 6 right_common | 7 left_common | 8 right_specific
// ---------------------------------------------------------------------------
extern "C" void kernel_launch(void* const* d_in, const int* in_sizes, int n_in,
                              void* d_out, int out_size)
{
    const float* emb   = (const float*)d_in[0];
    const int*   s2row = (const int*)  d_in[1];
    const int*   s3row = (const int*)  d_in[3];
    const int*   lspec = (const int*)  d_in[5];
    const int*   rcom  = (const int*)  d_in[6];
    const int*   lcom  = (const int*)  d_in[7];
    const int*   rspec = (const int*)  d_in[8];
    float*       out   = (float*)d_out;

    const int n_ent = in_sizes[5];
    const int n_typ = in_sizes[6];
    const int deg2  = in_sizes[1] / n_typ;
    const int deg3  = in_sizes[3] / in_sizes[8];

    // ---- sub2 ----
    sub2_kernel<<<n_typ, 512>>>(emb, s2row, lspec, rcom, out,
                                (float)n_ent - (float)deg2, deg2);

    // ---- sub3 ----
    const size_t smem_bytes = (size_t)n_typ * SLICE_V * sizeof(float4); // n_typ*64B
    if (deg3 == 4 && smem_bytes <= S3_SMEM_MAX) {
        static int attr_set = 0;
        if (!attr_set) {
            cudaFuncSetAttribute(sub3_smem,
                                 cudaFuncAttributeMaxDynamicSharedMemorySize,
                                 S3_SMEM_MAX);
            attr_set = 1;
        }
        dim3 grid(S3_GRIDX, NSLICE);
        sub3_smem<<<grid, S3_THREADS, smem_bytes>>>(
            (const float4*)emb, (const int4*)s3row, lcom, rspec,
            (float4*)out, n_ent, n_typ,
            (float)n_typ - 4.0f, 1.0f / 5.0f);
    } else {
        const int warps_per_block = 8;
        const int blocks = (n_ent + warps_per_block - 1) / warps_per_block;
        sub3_kernel_gen<<<blocks, warps_per_block * 32>>>(
            emb, s3row, lcom, rspec, out, n_ent, (float)n_typ, deg3);
    }
}